// round 14
// baseline (speedup 1.0000x reference)
#include <cuda_runtime.h>
#include <cstdint>
#include <math.h>

typedef unsigned long long ull;

__device__ __forceinline__ ull fma2(ull a, ull b, ull c) { ull d; asm("fma.rn.f32x2 %0,%1,%2,%3;":"=l"(d):"l"(a),"l"(b),"l"(c)); return d; }
__device__ __forceinline__ ull pk(float lo, float hi) { ull d; asm("mov.b64 %0,{%1,%2};":"=l"(d):"f"(lo),"f"(hi)); return d; }
__device__ __forceinline__ void upk(ull v, float& lo, float& hi) { asm("mov.b64 {%0,%1},%2;":"=f"(lo),"=f"(hi):"l"(v)); }
__device__ __forceinline__ unsigned s2u(const void* p){ unsigned r; asm("{.reg .u64 t; cvta.to.shared.u64 t, %1; cvt.u32.u64 %0, t;}":"=r"(r):"l"(p)); return r; }
__device__ __forceinline__ unsigned mapa_r(unsigned a, unsigned r){ unsigned o; asm("mapa.shared::cluster.u32 %0,%1,%2;":"=r"(o):"r"(a),"r"(r)); return o; }
__device__ __forceinline__ unsigned ctarank(){ unsigned r; asm("mov.u32 %0, %%cluster_ctarank;":"=r"(r)); return r; }
__device__ __forceinline__ void csync(){
    asm volatile("barrier.cluster.arrive.aligned;":::"memory");
    asm volatile("barrier.cluster.wait.aligned;":::"memory");
}
__device__ __forceinline__ void bar_init(unsigned bar, unsigned cnt){
    asm volatile("mbarrier.init.shared.b64 [%0], %1;" :: "r"(bar), "r"(cnt) : "memory");
}
__device__ __forceinline__ void bar_expect(unsigned bar, unsigned bytes){
    asm volatile("mbarrier.arrive.expect_tx.shared.b64 _, [%0], %1;" :: "r"(bar), "r"(bytes) : "memory");
}
__device__ __forceinline__ void bar_wait(unsigned bar, unsigned phase){
    unsigned done;
    asm volatile("{\n\t.reg .pred p;\n\t"
        "mbarrier.try_wait.parity.acquire.cta.shared::cta.b64 p, [%1], %2;\n\t"
        "selp.b32 %0, 1, 0, p;\n\t}"
        : "=r"(done) : "r"(bar), "r"(phase) : "memory");
    if (!done) {
        asm volatile("{\n\t.reg .pred P1;\n\t"
            "W_%=:\n\t"
            "mbarrier.try_wait.parity.acquire.cta.shared::cta.b64 P1, [%0], %1, 0x989680;\n\t"
            "@P1 bra.uni D_%=;\n\t"
            "bra.uni W_%=;\n\t"
            "D_%=:\n\t}"
            :: "r"(bar), "r"(phase) : "memory");
    }
}
__device__ __forceinline__ void fence_async(){
    asm volatile("fence.proxy.async.shared::cta;":::"memory");
}
__device__ __forceinline__ void blkcp_cluster(unsigned dst, unsigned src, unsigned bytes, unsigned rbar){
    asm volatile("cp.async.bulk.shared::cluster.shared::cta.mbarrier::complete_tx::bytes [%0], [%1], %2, [%3];"
        :: "r"(dst), "r"(src), "r"(bytes), "r"(rbar) : "memory");
}
__device__ __forceinline__ float tanh_fast(float x){
    float y; asm("tanh.approx.f32 %0, %1;" : "=f"(y) : "f"(x)); return y;
}

// ---------------- Phase A: xw = x @ W + b (f32x2, 128x128 tiles) -----------
// dir 0 -> out[b][t][j],  dir 1 -> out[b][511-t][512+j]
__global__ __launch_bounds__(256,2) void input_proj_kernel(
    const float* __restrict__ x,
    const float* __restrict__ Wf, const float* __restrict__ bf,
    const float* __restrict__ Wb, const float* __restrict__ bb,
    float* __restrict__ out)
{
    const int dir = blockIdx.z;
    const float* __restrict__ W = dir ? Wb : Wf;
    const float* __restrict__ bias = dir ? bb : bf;
    const int mBlk = blockIdx.x * 128;
    const int nBlk = blockIdx.y * 128;
    const int tid = threadIdx.x;

    __shared__ __align__(16) ull   As2[16][128];
    __shared__ __align__(16) float Bs[16][132];

    const int ar = tid >> 1, ac = (tid & 1) * 8;
    const int brow = tid >> 5, bcol = (tid & 31) * 4;
    const int tm = (tid >> 4) * 8, tn = (tid & 15) * 8;

    ull acc[8][4];
#pragma unroll
    for (int i = 0; i < 8; i++)
#pragma unroll
        for (int j = 0; j < 4; j++) acc[i][j] = 0ull;

    const float* aptr = x + (size_t)(mBlk + ar) * 512 + ac;
    const float* bptr = W + (size_t)brow * 512 + nBlk + bcol;

    for (int kk = 0; kk < 512; kk += 16) {
        const float4 av0 = *(const float4*)(aptr + kk);
        const float4 av1 = *(const float4*)(aptr + kk + 4);
        const float4 bv0 = *(const float4*)(bptr + (size_t)kk * 512);
        const float4 bv1 = *(const float4*)(bptr + (size_t)(kk + 8) * 512);
        __syncthreads();
        As2[ac + 0][ar] = pk(av0.x, av0.x);
        As2[ac + 1][ar] = pk(av0.y, av0.y);
        As2[ac + 2][ar] = pk(av0.z, av0.z);
        As2[ac + 3][ar] = pk(av0.w, av0.w);
        As2[ac + 4][ar] = pk(av1.x, av1.x);
        As2[ac + 5][ar] = pk(av1.y, av1.y);
        As2[ac + 6][ar] = pk(av1.z, av1.z);
        As2[ac + 7][ar] = pk(av1.w, av1.w);
        *(float4*)&Bs[brow][bcol]     = bv0;
        *(float4*)&Bs[brow + 8][bcol] = bv1;
        __syncthreads();
#pragma unroll
        for (int k = 0; k < 16; k++) {
            ull a2[8], b2[4];
#pragma unroll
            for (int u = 0; u < 4; u++)
                *(uint4*)&a2[u * 2] = *(const uint4*)&As2[k][tm + u * 2];
            *(uint4*)&b2[0] = *(const uint4*)&Bs[k][tn];
            *(uint4*)&b2[2] = *(const uint4*)&Bs[k][tn + 4];
#pragma unroll
            for (int i = 0; i < 8; i++)
#pragma unroll
                for (int j = 0; j < 4; j++)
                    acc[i][j] = fma2(a2[i], b2[j], acc[i][j]);
        }
    }

    float bo[8];
#pragma unroll
    for (int j = 0; j < 8; j++) bo[j] = bias[nBlk + tn + j];

#pragma unroll
    for (int i = 0; i < 8; i++) {
        const int m = mBlk + tm + i;
        const int b = m >> 9, t = m & 511;
        size_t addr;
        if (dir == 0) addr = (size_t)m * 1024 + (nBlk + tn);
        else          addr = ((size_t)(b << 9) + (511 - t)) * 1024 + 512 + (nBlk + tn);
        float v[8];
#pragma unroll
        for (int j = 0; j < 4; j++) {
            float lo, hi; upk(acc[i][j], lo, hi);
            v[2 * j] = lo + bo[2 * j]; v[2 * j + 1] = hi + bo[2 * j + 1];
        }
        *(float4*)(out + addr)     = *(float4*)&v[0];
        *(float4*)(out + addr + 4) = *(float4*)&v[4];
    }
}

// ---------------- Phase B: k-sliced cluster scan, 512 threads --------------
// 16 clusters x 8 CTAs x 512 thr. CTA rank owns U rows [64r,64r+64) packed as
// k-pairs P[kp][col]; h slice double-buffered as floats h2f[2][512] (layout
// [kp][row][parity] so matvec reads ull pairs). Matvec: 1 col/thread. Warp w
// produces half-slot (32 cols) for peer w>>1, pushes 1KB via cp.async.bulk
// with mbarrier tx-completion; consumer expects 16KB/step.
// red layout: float[2 buf][8 src][2 half][8 row][32 col]
#define SM_P    0                  // ull P[32][512]   = 131072 B
#define SM_H    131072             // float h2f[2][512]= 4096 B
#define SM_RED  135168             // 32768 B
#define SM_STG  167936             // [2][16][1024]    = 32768 B
#define SM_BAR  200704             // 16 B
#define SM_TOT  200736

__global__ void __cluster_dims__(8,1,1) __launch_bounds__(512,1)
scan_kernel(const float* __restrict__ Uf, const float* __restrict__ Ub,
            float* __restrict__ out)
{
    extern __shared__ __align__(16) char smem[];
    ull*   P   = (ull*)(smem + SM_P);
    float* h2f = (float*)(smem + SM_H);
    float* red = (float*)(smem + SM_RED);

    const unsigned rank = ctarank();
    const int cid = blockIdx.x >> 3;
    const int dir = cid >> 3;
    const int b0  = (cid & 7) * 8;
    const float* __restrict__ U = dir ? Ub : Uf;
    const int tid = threadIdx.x;
    const int k0 = (int)rank * 64;
    const unsigned sbase = s2u(smem);

    // one-time: pack own U k-slice as k-pairs, [kp][col]
    for (int i = tid; i < 32 * 512; i += 512) {
        const int kp = i >> 9, j = i & 511;
        const float u0 = U[(size_t)(k0 + 2 * kp) * 512 + j];
        const float u1 = U[(size_t)(k0 + 2 * kp + 1) * 512 + j];
        P[kp * 512 + j] = pk(u0, u1);
    }
    ((ull*)h2f)[tid] = 0ull;               // both buffers (512 ulls)
    if (tid == 0) { bar_init(sbase + SM_BAR, 1); bar_init(sbase + SM_BAR + 8, 1); }

    // compute role: col c = tid; peer = c>>6; half = (c>>5)&1
    const int c = tid;
    const unsigned peer = (unsigned)(c >> 6);
    const int half = (c >> 5) & 1;
    const int lane = c & 31;
    const unsigned predR = mapa_r(sbase + (unsigned)SM_RED, peer);
    const unsigned pbar  = mapa_r(sbase + (unsigned)SM_BAR, peer);
    const unsigned stg_off = (unsigned)SM_STG + (unsigned)((tid >> 5) * 1024);

    // reduce role: row rr = tid>>6, col cc = tid&63
    const int rr = tid >> 6;
    const int cc = tid & 63;
    const int jglob = (int)rank * 64 + cc;
    float* xwp = out + (((size_t)(b0 + rr) << 9)) * 1024 + (size_t)(dir << 9) + jglob;
    const int hwr = (cc >> 1) * 16 + rr * 2 + (cc & 1);   // h2f index within buffer

    csync();   // barriers + h2 + P visible cluster-wide

    for (int s = 0; s < 512; s++) {
        const int buf = s & 1;
        const unsigned lbar = sbase + (unsigned)SM_BAR + (unsigned)(buf * 8);
        if (tid == 0) bar_expect(lbar, 16384);

        const float xv = xwp[(size_t)s * 1024];   // prefetch

        ull acc[8];
#pragma unroll
        for (int r = 0; r < 8; r++) acc[r] = 0ull;

        const ull* hc = (const ull*)h2f + buf * 256;
#pragma unroll 4
        for (int kp = 0; kp < 32; kp++) {
            ull hp[8];
#pragma unroll
            for (int q = 0; q < 4; q++)
                *(uint4*)&hp[q * 2] = *(const uint4*)&hc[kp * 8 + q * 2];
            const ull u = P[kp * 512 + c];
#pragma unroll
            for (int r = 0; r < 8; r++)
                acc[r] = fma2(hp[r], u, acc[r]);
        }

        // stage this warp's half-slot: [8 rows][32 cols] floats = 1KB
        float* st = (float*)(smem + stg_off + (unsigned)(buf * 16384));
#pragma unroll
        for (int r = 0; r < 8; r++) {
            float a, b; upk(acc[r], a, b);
            st[r * 32 + lane] = a + b;
        }
        __syncwarp();
        if (lane == 0) {
            fence_async();
            blkcp_cluster(predR + (unsigned)(buf * 16384 + (int)rank * 2048 + half * 1024),
                          sbase + stg_off + (unsigned)(buf * 16384),
                          1024u, pbar + (unsigned)(buf * 8));
        }

        bar_wait(lbar, (unsigned)((s >> 1) & 1));

        // reduce own slice: sum 8 srcs + xw, tanh
        const float* rp = red + buf * 4096 + (cc >> 5) * 256 + rr * 32 + (cc & 31);
        float s0 = xv;
#pragma unroll
        for (int q = 0; q < 8; q++) s0 += rp[q * 512];
        const float y = tanh_fast(s0);
        xwp[(size_t)s * 1024] = y;
        h2f[(buf ^ 1) * 512 + hwr] = y;
        __syncthreads();
    }
    csync();   // no CTA exits while peers may still push into its smem
}

extern "C" void kernel_launch(void* const* d_in, const int* in_sizes, int n_in,
                              void* d_out, int out_size) {
    const float* x  = (const float*)d_in[0];
    const float* Wf = (const float*)d_in[1];
    const float* Uf = (const float*)d_in[2];
    const float* bf = (const float*)d_in[3];
    const float* Wb = (const float*)d_in[4];
    const float* Ub = (const float*)d_in[5];
    const float* bb = (const float*)d_in[6];
    float* out = (float*)d_out;
    (void)in_sizes; (void)n_in; (void)out_size;

    dim3 gA(256, 4, 2);
    input_proj_kernel<<<gA, 256>>>(x, Wf, bf, Wb, bb, out);

    cudaFuncSetAttribute(scan_kernel,
                         cudaFuncAttributeMaxDynamicSharedMemorySize, SM_TOT);
    scan_kernel<<<128, 512, SM_TOT>>>(Uf, Ub, out);
}